// round 7
// baseline (speedup 1.0000x reference)
#include <cuda_runtime.h>

#define BB 8
#define LL 1024
#define DD 512
#define HD 4096

// Accumulators. Zero at module load (first call OK); k4's epilogue re-zeroes
// xsum2/vsum4 for the next replay; zc re-zeroed by kA's extra blocks each call.
__device__ __align__(16) float g_xsum2[2][BB * DD];   // 32 KB
__device__ __align__(16) float g_vsum4[4][BB * HD];   // 512 KB
__device__ __align__(16) float g_zc[8][BB * DD];      // 128 KB

__device__ __forceinline__ void red_add_v4(float* a, float4 v) {
    asm volatile("red.global.add.v4.f32 [%0], {%1,%2,%3,%4};"
                 :: "l"(a), "f"(v.x), "f"(v.y), "f"(v.z), "f"(v.w) : "memory");
}

// kA: blocks [0,512): xsum += input over 16-row chunks (red into 2 copies).
//     blocks [512,544): zero g_zc for this call.
__global__ __launch_bounds__(256) void kA(const float* __restrict__ x) {
    int blk = blockIdx.x, t = threadIdx.x;
    if (blk >= 512) {
        int q = (blk - 512) * 256 + t;   // 8192 quads
        reinterpret_cast<float4*>(&g_zc[0][0])[q] = make_float4(0.f, 0.f, 0.f, 0.f);
        return;
    }
    int b = blk >> 6, c = blk & 63;          // 64 L-chunks of 16 rows
    int h = t >> 7, q = t & 127;             // 8-row half, quad
    const float4* p = reinterpret_cast<const float4*>(x)
                    + (size_t)b * LL * 128 + (size_t)(c * 16 + h * 8) * 128 + q;
    float4 s = make_float4(0.f, 0.f, 0.f, 0.f);
#pragma unroll
    for (int r = 0; r < 8; ++r) {
        float4 v = p[r * 128];
        s.x += v.x; s.y += v.y; s.z += v.z; s.w += v.w;
    }
    red_add_v4(&g_xsum2[h][b * DD + 4 * q], s);
}

// k2: vsum += xsum @ wv (+ L*bv on kc==0).  wv is [DD x HD] row-major.
// grid (jb=8, kc=32), 512 threads; 32 KB tile; in-block kg-half combine.
__global__ void k2_vsum(const float* __restrict__ wv, const float* __restrict__ bv) {
    __shared__ float4 sw[16 * 128];   // 32 KB
    __shared__ float4 sc[256 * 4];    // 16 KB; first 512 B doubles as xs
    float* xs = reinterpret_cast<float*>(sc);

    int t = threadIdx.x;
    int jb = blockIdx.x, kc = blockIdx.y;
    int k0 = kc * 16;

    const float4* w4 = reinterpret_cast<const float4*>(wv);
#pragma unroll
    for (int u = 0; u < 4; ++u) {
        int g = t + u * 512;
        int kk = g >> 7, jq = g & 127;
        sw[g] = w4[(size_t)(k0 + kk) * (HD / 4) + jb * 128 + jq];
    }
    if (t < 128) {
        int b = t >> 4, kk = t & 15;
        int a = b * DD + k0 + kk;
        xs[t] = g_xsum2[0][a] + g_xsum2[1][a];
    }
    __syncthreads();

    int jq = t & 127, kg = (t >> 7) & 1, bg = t >> 8;
    float4 acc[4];
#pragma unroll
    for (int i = 0; i < 4; ++i) acc[i] = make_float4(0.f, 0.f, 0.f, 0.f);
#pragma unroll
    for (int kk = 0; kk < 8; ++kk) {
        float4 wq = sw[(kg * 8 + kk) * 128 + jq];
#pragma unroll
        for (int bi = 0; bi < 4; ++bi) {
            float xv = xs[(bg * 4 + bi) * 16 + kg * 8 + kk];
            acc[bi].x += xv * wq.x; acc[bi].y += xv * wq.y;
            acc[bi].z += xv * wq.z; acc[bi].w += xv * wq.w;
        }
    }
    __syncthreads();
    int slot = (bg * 128 + jq) * 4;
    if (kg == 1) {
#pragma unroll
        for (int bi = 0; bi < 4; ++bi) sc[slot + bi] = acc[bi];
    }
    __syncthreads();
    if (kg == 0) {
        float4 lb = make_float4(0.f, 0.f, 0.f, 0.f);
        if (kc == 0) {
            float4 bv4 = reinterpret_cast<const float4*>(bv)[jb * 128 + jq];
            lb.x = 1024.f * bv4.x; lb.y = 1024.f * bv4.y;
            lb.z = 1024.f * bv4.z; lb.w = 1024.f * bv4.w;
        }
        float* base = &g_vsum4[kc & 3][0];
#pragma unroll
        for (int bi = 0; bi < 4; ++bi) {
            float4 o = sc[slot + bi];
            o.x += acc[bi].x + lb.x; o.y += acc[bi].y + lb.y;
            o.z += acc[bi].z + lb.z; o.w += acc[bi].w + lb.w;
            red_add_v4(base + (bg * 4 + bi) * HD + jb * 512 + 4 * jq, o);
        }
    }
}

// k3: zc += vsum @ fc_w (+ fc_b on jc==0).  fc_w is [HD x DD] row-major.
// grid 256 (j-chunks of 16), 512 threads; 32 KB tile; jg-half combine.
__global__ void k3_z(const float* __restrict__ fcw, const float* __restrict__ fcb) {
    __shared__ float4 sw[16 * 128];
    __shared__ float4 sc[256 * 4];
    float* vs = reinterpret_cast<float*>(sc);

    int t = threadIdx.x;
    int jc = blockIdx.x;
    int j0 = jc * 16;

    const float4* w4 = reinterpret_cast<const float4*>(fcw);
#pragma unroll
    for (int u = 0; u < 4; ++u) {
        int g = t + u * 512;
        int jj = g >> 7, iq = g & 127;
        sw[g] = w4[(size_t)(j0 + jj) * (DD / 4) + iq];
    }
    if (t < 128) {
        int b = t >> 4, jj = t & 15;
        int a = b * HD + j0 + jj;
        vs[t] = g_vsum4[0][a] + g_vsum4[1][a] + g_vsum4[2][a] + g_vsum4[3][a];
    }
    __syncthreads();

    int iq = t & 127, jg = (t >> 7) & 1, bg = t >> 8;
    float4 acc[4];
#pragma unroll
    for (int i = 0; i < 4; ++i) acc[i] = make_float4(0.f, 0.f, 0.f, 0.f);
#pragma unroll
    for (int jj = 0; jj < 8; ++jj) {
        float4 wq = sw[(jg * 8 + jj) * 128 + iq];
#pragma unroll
        for (int bi = 0; bi < 4; ++bi) {
            float vv = vs[(bg * 4 + bi) * 16 + jg * 8 + jj];
            acc[bi].x += vv * wq.x; acc[bi].y += vv * wq.y;
            acc[bi].z += vv * wq.z; acc[bi].w += vv * wq.w;
        }
    }
    __syncthreads();
    int slot = (bg * 128 + iq) * 4;
    if (jg == 1) {
#pragma unroll
        for (int bi = 0; bi < 4; ++bi) sc[slot + bi] = acc[bi];
    }
    __syncthreads();
    if (jg == 0) {
        float4 fb = make_float4(0.f, 0.f, 0.f, 0.f);
        if (jc == 0) fb = reinterpret_cast<const float4*>(fcb)[iq];
        float* base = &g_zc[jc & 7][0];
#pragma unroll
        for (int bi = 0; bi < 4; ++bi) {
            float4 o = sc[slot + bi];
            o.x += acc[bi].x + fb.x; o.y += acc[bi].y + fb.y;
            o.z += acc[bi].z + fb.z; o.w += acc[bi].w + fb.w;
            red_add_v4(base + (bg * 4 + bi) * DD + 4 * iq, o);
        }
    }
}

// k4: out = LayerNorm(merge(zc)[b] + x[b,l]) * g + beta.
// 512 blocks x 256 threads, two rows per warp, TWO-PASS: pass A streams x to
// build (s,q); pass B re-reads x (L1-hit: 32 KB/block) to normalize+store.
// No x retention -> ~48 regs -> 5 blocks/SM (launch_bounds).
__global__ __launch_bounds__(256, 5) void k4_ln(
        const float* __restrict__ x,
        const float* __restrict__ lng, const float* __restrict__ lnb,
        float* __restrict__ out) {
    __shared__ float4 zs[128];
    int t = threadIdx.x, blk = blockIdx.x;
    int b = blk >> 6;                      // 64 blocks (16 rows each) per batch

    if (t < 128) {
        float4 s = make_float4(0.f, 0.f, 0.f, 0.f);
#pragma unroll
        for (int c = 0; c < 8; ++c) {
            float4 v = reinterpret_cast<const float4*>(&g_zc[c][0])[b * 128 + t];
            s.x += v.x; s.y += v.y; s.z += v.z; s.w += v.w;
        }
        zs[t] = s;
    }
    __syncthreads();

    int warp = t >> 5, lane = t & 31;
    int row0 = blk * 16 + warp * 2;

    const float4* xp0 = reinterpret_cast<const float4*>(x) + (size_t)row0 * 128;
    const float4* xp1 = xp0 + 128;

    // Pass A: accumulate sums only (no retention).
    float sa = 0.f, qa = 0.f, sb = 0.f, qb = 0.f;
#pragma unroll
    for (int i = 0; i < 4; ++i) {
        float4 va = xp0[lane + 32 * i];
        float4 vb = xp1[lane + 32 * i];
        float4 z  = zs[lane + 32 * i];
        float y;
        y = va.x + z.x; sa += y; qa += y * y;
        y = va.y + z.y; sa += y; qa += y * y;
        y = va.z + z.z; sa += y; qa += y * y;
        y = va.w + z.w; sa += y; qa += y * y;
        y = vb.x + z.x; sb += y; qb += y * y;
        y = vb.y + z.y; sb += y; qb += y * y;
        y = vb.z + z.z; sb += y; qb += y * y;
        y = vb.w + z.w; sb += y; qb += y * y;
    }
#pragma unroll
    for (int o = 16; o > 0; o >>= 1) {
        sa += __shfl_xor_sync(0xFFFFFFFFu, sa, o);
        qa += __shfl_xor_sync(0xFFFFFFFFu, qa, o);
        sb += __shfl_xor_sync(0xFFFFFFFFu, sb, o);
        qb += __shfl_xor_sync(0xFFFFFFFFu, qb, o);
    }
    float mua  = sa * (1.0f / DD);
    float inva = rsqrtf(qa * (1.0f / DD) - mua * mua + 1e-5f);
    float mub  = sb * (1.0f / DD);
    float invb = rsqrtf(qb * (1.0f / DD) - mub * mub + 1e-5f);

    // Pass B: re-read x (L1 hits), normalize, store.
    const float4* gp = reinterpret_cast<const float4*>(lng);
    const float4* bp = reinterpret_cast<const float4*>(lnb);
    float4* op0 = reinterpret_cast<float4*>(out) + (size_t)row0 * 128;
    float4* op1 = op0 + 128;
#pragma unroll
    for (int i = 0; i < 4; ++i) {
        float4 va = xp0[lane + 32 * i];
        float4 vb = xp1[lane + 32 * i];
        float4 z  = zs[lane + 32 * i];
        float4 gv = gp[lane + 32 * i];
        float4 be = bp[lane + 32 * i];
        float4 o;
        o.x = (va.x + z.x - mua) * inva * gv.x + be.x;
        o.y = (va.y + z.y - mua) * inva * gv.y + be.y;
        o.z = (va.z + z.z - mua) * inva * gv.z + be.z;
        o.w = (va.w + z.w - mua) * inva * gv.w + be.w;
        op0[lane + 32 * i] = o;
        o.x = (vb.x + z.x - mub) * invb * gv.x + be.x;
        o.y = (vb.y + z.y - mub) * invb * gv.y + be.y;
        o.z = (vb.z + z.z - mub) * invb * gv.z + be.z;
        o.w = (vb.w + z.w - mub) * invb * gv.w + be.w;
        op1[lane + 32 * i] = o;
    }

    // Epilogue resets for next replay (k4 reads neither buffer).
    float4 z4 = make_float4(0.f, 0.f, 0.f, 0.f);
    if (t < 64)
        reinterpret_cast<float4*>(&g_vsum4[0][0])[blk * 64 + t] = z4;   // 32768 quads
    if (t < 4)
        reinterpret_cast<float4*>(&g_xsum2[0][0])[blk * 4 + t] = z4;    // 2048 quads
}

extern "C" void kernel_launch(void* const* d_in, const int* in_sizes, int n_in,
                              void* d_out, int out_size) {
    const float* input = (const float*)d_in[0];
    const float* wv    = (const float*)d_in[5];
    const float* bv    = (const float*)d_in[6];
    const float* fcw   = (const float*)d_in[9];
    const float* fcb   = (const float*)d_in[10];
    const float* lng   = (const float*)d_in[11];
    const float* lnb   = (const float*)d_in[12];
    float* out = (float*)d_out;

    kA     <<<544, 256>>>(input);
    k2_vsum<<<dim3(8, 32), 512>>>(wv, bv);
    k3_z   <<<256, 512>>>(fcw, fcb);
    k4_ln  <<<512, 256>>>(input, lng, lnb, out);
}